// round 1
// baseline (speedup 1.0000x reference)
#include <cuda_runtime.h>
#include <math.h>

// Problem-fixed dimensions (from reference setup_inputs)
#define NNODES 100000
#define NEDGES 1600000
#define CIN 64
#define CH 128          // hidden = out channels
#define ROWS 16         // rows per block in GEMM-style kernels

// Scratch (allocation-free rule: __device__ globals)
__device__ __align__(128) float g_bufA[(size_t)NNODES * CH];
__device__ __align__(128) float g_bufB[(size_t)NNODES * CH];
__device__ __align__(128) float g_dinv[NNODES];
__device__ __align__(128) float g_stats[2 * CH];   // per-channel sum / sumsq
__device__ int g_idx32;                            // 1 if edge_index stored as int32

// ---------------------------------------------------------------------------
// Detect edge_index dtype: int64 values < 2^31 -> odd 32-bit words are zero.
// ---------------------------------------------------------------------------
__global__ void detect_idx_kernel(const int* __restrict__ ei) {
    __shared__ int s_any;
    if (threadIdx.x == 0) s_any = 0;
    __syncthreads();
    int any = 0;
    // check odd words among first 4096 int32 words (covers 2048 edges)
    for (int i = 1 + 2 * threadIdx.x; i < 4096; i += 2 * blockDim.x)
        any |= ei[i];
    if (any) atomicOr(&s_any, 1);
    __syncthreads();
    if (threadIdx.x == 0) g_idx32 = (s_any != 0) ? 1 : 0;
}

__device__ __forceinline__ void load_edge(const void* ei, int e, int& src, int& dst) {
    if (g_idx32) {
        const int* p = (const int*)ei;
        src = p[e];
        dst = p[NEDGES + e];
    } else {
        const long long* p = (const long long*)ei;
        src = (int)p[e];
        dst = (int)p[NEDGES + e];
    }
}

// ---------------------------------------------------------------------------
// Degree: deg[i] = 1 (self loop) + sum_{e: dst==i} w[e];   dinv = rsqrt(deg)
// ---------------------------------------------------------------------------
__global__ void deg_init_kernel() {
    int i = blockIdx.x * blockDim.x + threadIdx.x;
    if (i < NNODES) g_dinv[i] = 1.0f;
}

__global__ void deg_accum_kernel(const void* __restrict__ ei,
                                 const float* __restrict__ ew) {
    int e = blockIdx.x * blockDim.x + threadIdx.x;
    if (e >= NEDGES) return;
    int src, dst;
    load_edge(ei, e, src, dst);
    atomicAdd(&g_dinv[dst], ew[e]);
}

__global__ void deg_finalize_kernel() {
    int i = blockIdx.x * blockDim.x + threadIdx.x;
    if (i < NNODES) g_dinv[i] = rsqrtf(g_dinv[i]);
}

// ---------------------------------------------------------------------------
// GEMM: C[N x 128] = A[N x K] @ W[K x 128]
// 128 threads/block (one per output column), ROWS=16 rows/block.
// ---------------------------------------------------------------------------
template <int K>
__global__ __launch_bounds__(128) void gemm_kernel(const float* __restrict__ A,
                                                   const float* __restrict__ W,
                                                   float* __restrict__ C) {
    __shared__ float xs[ROWS][K];
    const int row0 = blockIdx.x * ROWS;
    const int tid = threadIdx.x;

    const float4* A4 = (const float4*)(A + (size_t)row0 * K);
    float4* xs4 = (float4*)&xs[0][0];
#pragma unroll
    for (int i = tid; i < ROWS * K / 4; i += 128) xs4[i] = A4[i];
    __syncthreads();

    float acc[ROWS];
#pragma unroll
    for (int r = 0; r < ROWS; r++) acc[r] = 0.0f;

#pragma unroll 4
    for (int k = 0; k < K; k++) {
        float wv = W[k * CH + tid];
#pragma unroll
        for (int r = 0; r < ROWS; r++) acc[r] += xs[r][k] * wv;
    }

    float* Cp = C + (size_t)row0 * CH + tid;
#pragma unroll
    for (int r = 0; r < ROWS; r++) Cp[(size_t)r * CH] = acc[r];
}

// ---------------------------------------------------------------------------
// Aggregation init: out[i][c] = b[c] + dinv[i]^2 * h[i][c]   (self-loop term)
// Also zeroes the BN stats accumulators (block 0).
// ---------------------------------------------------------------------------
__global__ void agg_init_kernel(const float* __restrict__ h,
                                const float* __restrict__ b,
                                float* __restrict__ out) {
    if (blockIdx.x == 0 && threadIdx.x < 2 * CH) g_stats[threadIdx.x] = 0.0f;
    int idx = blockIdx.x * blockDim.x + threadIdx.x;   // float4 index
    const int total = NNODES * CH / 4;
    if (idx >= total) return;
    int row = idx >> 5;            // 32 float4 per row
    int c4 = (idx & 31) * 4;
    float di = g_dinv[row];
    float s = di * di;
    float4 hv = ((const float4*)h)[idx];
    float4 o;
    o.x = b[c4 + 0] + s * hv.x;
    o.y = b[c4 + 1] + s * hv.y;
    o.z = b[c4 + 2] + s * hv.z;
    o.w = b[c4 + 3] + s * hv.w;
    ((float4*)out)[idx] = o;
}

// ---------------------------------------------------------------------------
// Edge aggregation: out[dst] += dinv[src]*w*dinv[dst] * h[src]
// One warp per edge; each lane owns 4 contiguous channels.
// ---------------------------------------------------------------------------
__global__ __launch_bounds__(256) void edge_agg_kernel(const void* __restrict__ ei,
                                                       const float* __restrict__ ew,
                                                       const float* __restrict__ h,
                                                       float* __restrict__ out) {
    int t = blockIdx.x * blockDim.x + threadIdx.x;
    int e = t >> 5;
    int lane = t & 31;
    if (e >= NEDGES) return;
    int src, dst;
    load_edge(ei, e, src, dst);
    float w = ew[e];
    float norm = g_dinv[src] * w * g_dinv[dst];
    float4 v = ((const float4*)(h + (size_t)src * CH))[lane];
    float* o = out + (size_t)dst * CH + lane * 4;
    atomicAdd(o + 0, norm * v.x);
    atomicAdd(o + 1, norm * v.y);
    atomicAdd(o + 2, norm * v.z);
    atomicAdd(o + 3, norm * v.w);
}

// ---------------------------------------------------------------------------
// BatchNorm stats: per-channel sum and sumsq (block partials + atomics)
// ---------------------------------------------------------------------------
__global__ __launch_bounds__(128) void bn_stats_kernel(const float* __restrict__ h) {
    int c = threadIdx.x;                  // 128 channels
    int row0 = blockIdx.x * 128;
    int rend = min(row0 + 128, NNODES);
    float s = 0.0f, s2 = 0.0f;
    for (int r = row0; r < rend; r++) {
        float v = h[(size_t)r * CH + c];
        s += v;
        s2 += v * v;
    }
    atomicAdd(&g_stats[c], s);
    atomicAdd(&g_stats[CH + c], s2);
}

// ---------------------------------------------------------------------------
// BN apply + ReLU (in place): y = max(0, x*scale + shift)
// ---------------------------------------------------------------------------
__global__ __launch_bounds__(256) void bn_apply_kernel(float* __restrict__ h,
                                                       const float* __restrict__ gamma,
                                                       const float* __restrict__ beta) {
    __shared__ float sc[CH], sh[CH];
    if (threadIdx.x < CH) {
        float mean = g_stats[threadIdx.x] * (1.0f / NNODES);
        float var = g_stats[CH + threadIdx.x] * (1.0f / NNODES) - mean * mean;
        float scale = gamma[threadIdx.x] * rsqrtf(var + 1e-5f);
        sc[threadIdx.x] = scale;
        sh[threadIdx.x] = beta[threadIdx.x] - mean * scale;
    }
    __syncthreads();
    const int total = NNODES * CH / 4;
    for (int idx = blockIdx.x * blockDim.x + threadIdx.x; idx < total;
         idx += gridDim.x * blockDim.x) {
        float4 v = ((float4*)h)[idx];
        int c4 = (idx & 31) * 4;
        v.x = fmaxf(v.x * sc[c4 + 0] + sh[c4 + 0], 0.0f);
        v.y = fmaxf(v.y * sc[c4 + 1] + sh[c4 + 1], 0.0f);
        v.z = fmaxf(v.z * sc[c4 + 2] + sh[c4 + 2], 0.0f);
        v.w = fmaxf(v.w * sc[c4 + 3] + sh[c4 + 3], 0.0f);
        ((float4*)h)[idx] = v;
    }
}

// ---------------------------------------------------------------------------
// Final fused layer:
// out = [h | relu(dist*Wd+bd) | relu(deg*Wg+bg)] @ Wm + bm
// ---------------------------------------------------------------------------
__global__ __launch_bounds__(128) void final_kernel(const float* __restrict__ h,
                                                    const float* __restrict__ dist,
                                                    const float* __restrict__ degf,
                                                    const float* __restrict__ Wd,
                                                    const float* __restrict__ bd,
                                                    const float* __restrict__ Wg,
                                                    const float* __restrict__ bg,
                                                    const float* __restrict__ Wm,
                                                    const float* __restrict__ bm,
                                                    float* __restrict__ out) {
    __shared__ float hs[ROWS][CH];
    __shared__ float dfs[ROWS][CH];
    __shared__ float gfs[ROWS][CH];
    const int row0 = blockIdx.x * ROWS;
    const int tid = threadIdx.x;

    const float4* h4 = (const float4*)(h + (size_t)row0 * CH);
#pragma unroll
    for (int i = tid; i < ROWS * CH / 4; i += 128) ((float4*)&hs[0][0])[i] = h4[i];

    float wd = Wd[tid], bdv = bd[tid], wg = Wg[tid], bgv = bg[tid];
#pragma unroll
    for (int r = 0; r < ROWS; r++) {
        dfs[r][tid] = fmaxf(dist[row0 + r] * wd + bdv, 0.0f);
        gfs[r][tid] = fmaxf(degf[row0 + r] * wg + bgv, 0.0f);
    }
    __syncthreads();

    float acc[ROWS];
    float bmv = bm[tid];
#pragma unroll
    for (int r = 0; r < ROWS; r++) acc[r] = bmv;

#pragma unroll 2
    for (int j = 0; j < CH; j++) {
        float w1 = Wm[(size_t)j * CH + tid];
        float w2 = Wm[(size_t)(CH + j) * CH + tid];
        float w3 = Wm[(size_t)(2 * CH + j) * CH + tid];
#pragma unroll
        for (int r = 0; r < ROWS; r++)
            acc[r] += hs[r][j] * w1 + dfs[r][j] * w2 + gfs[r][j] * w3;
    }

    float* op = out + (size_t)row0 * CH + tid;
#pragma unroll
    for (int r = 0; r < ROWS; r++) op[(size_t)r * CH] = acc[r];
}

// ---------------------------------------------------------------------------
extern "C" void kernel_launch(void* const* d_in, const int* in_sizes, int n_in,
                              void* d_out, int out_size) {
    const float* x     = (const float*)d_in[0];
    const void*  ei    = d_in[1];
    const float* ew    = (const float*)d_in[2];
    const float* dist  = (const float*)d_in[3];
    const float* degf  = (const float*)d_in[4];
    const float* W1    = (const float*)d_in[5];
    const float* b1    = (const float*)d_in[6];
    const float* W2    = (const float*)d_in[7];
    const float* b2    = (const float*)d_in[8];
    const float* g1    = (const float*)d_in[9];
    const float* be1   = (const float*)d_in[10];
    const float* g2    = (const float*)d_in[11];
    const float* be2   = (const float*)d_in[12];
    const float* Wd    = (const float*)d_in[13];
    const float* bd    = (const float*)d_in[14];
    const float* Wg    = (const float*)d_in[15];
    const float* bg    = (const float*)d_in[16];
    const float* Wm    = (const float*)d_in[17];
    const float* bm    = (const float*)d_in[18];
    float* out = (float*)d_out;

    float *bufA, *bufB;
    cudaGetSymbolAddress((void**)&bufA, g_bufA);
    cudaGetSymbolAddress((void**)&bufB, g_bufB);

    const int nodeBlocks = (NNODES + 255) / 256;
    const int edgeBlocks = (NEDGES + 255) / 256;
    const int rowBlocks  = NNODES / ROWS;          // 6250 (exact)
    const int elemBlocks = (NNODES * CH / 4 + 255) / 256;
    const int aggBlocks  = (NEDGES * 32 + 255) / 256;

    // --- gcn_norm ---
    detect_idx_kernel<<<1, 256>>>((const int*)ei);
    deg_init_kernel<<<nodeBlocks, 256>>>();
    deg_accum_kernel<<<edgeBlocks, 256>>>(ei, ew);
    deg_finalize_kernel<<<nodeBlocks, 256>>>();

    // --- layer 1: conv + BN + ReLU ---
    gemm_kernel<CIN><<<rowBlocks, 128>>>(x, W1, bufA);
    agg_init_kernel<<<elemBlocks, 256>>>(bufA, b1, bufB);
    edge_agg_kernel<<<aggBlocks, 256>>>(ei, ew, bufA, bufB);
    bn_stats_kernel<<<(NNODES + 127) / 128, 128>>>(bufB);
    bn_apply_kernel<<<2048, 256>>>(bufB, g1, be1);

    // --- layer 2: conv + BN + ReLU ---
    gemm_kernel<CH><<<rowBlocks, 128>>>(bufB, W2, bufA);
    agg_init_kernel<<<elemBlocks, 256>>>(bufA, b2, bufB);
    edge_agg_kernel<<<aggBlocks, 256>>>(ei, ew, bufA, bufB);
    bn_stats_kernel<<<(NNODES + 127) / 128, 128>>>(bufB);
    bn_apply_kernel<<<2048, 256>>>(bufB, g2, be2);

    // --- final fused projection ---
    final_kernel<<<rowBlocks, 128>>>(bufB, dist, degf, Wd, bd, Wg, bg, Wm, bm, out);
}

// round 2
// speedup vs baseline: 1.5720x; 1.5720x over previous
#include <cuda_runtime.h>
#include <math.h>

// Problem-fixed dimensions (from reference setup_inputs)
#define NNODES 100000
#define NEDGES 1600000
#define CIN 64
#define CH 128          // hidden = out channels
#define ROWS 32         // rows per block in GEMM-style kernels (100000/32 = 3125 exact)

// Scratch (allocation-free rule: __device__ globals)
__device__ __align__(128) float g_bufA[(size_t)NNODES * CH];
__device__ __align__(128) float g_bufB[(size_t)NNODES * CH];
__device__ __align__(128) float g_dinv[NNODES];
__device__ __align__(128) float g_stats[2 * CH];     // per-channel sum / sumsq
__device__ __align__(128) int   g_rowptr[NNODES + 1];
__device__ __align__(128) int   g_cursor[NNODES];
__device__ __align__(128) int   g_csr_src[NEDGES];
__device__ __align__(128) float g_csr_norm[NEDGES];
__device__ int g_idx32;                              // 1 if edge_index stored as int32

// ---------------------------------------------------------------------------
// Detect edge_index dtype: int64 values < 2^31 -> odd 32-bit words are zero.
// ---------------------------------------------------------------------------
__global__ void detect_idx_kernel(const int* __restrict__ ei) {
    __shared__ int s_any;
    if (threadIdx.x == 0) s_any = 0;
    __syncthreads();
    int any = 0;
    for (int i = 1 + 2 * threadIdx.x; i < 4096; i += 2 * blockDim.x)
        any |= ei[i];
    if (any) atomicOr(&s_any, 1);
    __syncthreads();
    if (threadIdx.x == 0) g_idx32 = (s_any != 0) ? 1 : 0;
}

__device__ __forceinline__ void load_edge(const void* ei, int e, int& src, int& dst) {
    if (g_idx32) {
        const int* p = (const int*)ei;
        src = p[e];
        dst = p[NEDGES + e];
    } else {
        const long long* p = (const long long*)ei;
        src = (int)p[e];
        dst = (int)p[NEDGES + e];
    }
}

// ---------------------------------------------------------------------------
// Init: dinv = 1 (self loop weight), counts = 0
// ---------------------------------------------------------------------------
__global__ void deg_init_kernel() {
    int i = blockIdx.x * blockDim.x + threadIdx.x;
    if (i < NNODES) {
        g_dinv[i] = 1.0f;
        g_cursor[i] = 0;    // used as in-degree count first
    }
}

// deg[dst] += w ; count[dst] += 1
__global__ void deg_count_kernel(const void* __restrict__ ei,
                                 const float* __restrict__ ew) {
    int e = blockIdx.x * blockDim.x + threadIdx.x;
    if (e >= NEDGES) return;
    int src, dst;
    load_edge(ei, e, src, dst);
    atomicAdd(&g_dinv[dst], ew[e]);
    atomicAdd(&g_cursor[dst], 1);
}

__global__ void deg_finalize_kernel() {
    int i = blockIdx.x * blockDim.x + threadIdx.x;
    if (i < NNODES) g_dinv[i] = rsqrtf(g_dinv[i]);
}

// ---------------------------------------------------------------------------
// Single-block exclusive scan of counts -> rowptr; cursor = rowptr copy.
// ---------------------------------------------------------------------------
#define SCAN_T 1024
__global__ __launch_bounds__(SCAN_T) void scan_kernel() {
    __shared__ int ssum[SCAN_T];
    const int CHUNK = (NNODES + SCAN_T - 1) / SCAN_T;   // 98
    int t = threadIdx.x;
    int start = t * CHUNK;
    int end = min(start + CHUNK, NNODES);
    int s = 0;
    for (int i = start; i < end; i++) s += g_cursor[i];
    ssum[t] = s;
    __syncthreads();
    // Hillis-Steele inclusive scan
    for (int off = 1; off < SCAN_T; off <<= 1) {
        int v = (t >= off) ? ssum[t - off] : 0;
        __syncthreads();
        ssum[t] += v;
        __syncthreads();
    }
    int run = (t == 0) ? 0 : ssum[t - 1];
    for (int i = start; i < end; i++) {
        int c = g_cursor[i];
        g_rowptr[i] = run;
        g_cursor[i] = run;      // write cursor for fill pass
        run += c;
    }
    if (t == SCAN_T - 1) g_rowptr[NNODES] = run;
}

// ---------------------------------------------------------------------------
// Fill CSR: for each edge, place (src, norm) into its dst's row.
// norm = dinv[src] * w * dinv[dst]
// ---------------------------------------------------------------------------
__global__ void fill_kernel(const void* __restrict__ ei,
                            const float* __restrict__ ew) {
    int e = blockIdx.x * blockDim.x + threadIdx.x;
    if (e >= NEDGES) return;
    int src, dst;
    load_edge(ei, e, src, dst);
    float norm = g_dinv[src] * ew[e] * g_dinv[dst];
    int pos = atomicAdd(&g_cursor[dst], 1);
    g_csr_src[pos] = src;
    g_csr_norm[pos] = norm;
}

// ---------------------------------------------------------------------------
// GEMM: C[N x 128] = A[N x K] @ W[K x 128]
// 128 threads/block (one per output column), ROWS rows/block.
// ---------------------------------------------------------------------------
template <int K>
__global__ __launch_bounds__(128) void gemm_kernel(const float* __restrict__ A,
                                                   const float* __restrict__ W,
                                                   float* __restrict__ C) {
    __shared__ float xs[ROWS][K];
    const int row0 = blockIdx.x * ROWS;
    const int tid = threadIdx.x;

    const float4* A4 = (const float4*)(A + (size_t)row0 * K);
    float4* xs4 = (float4*)&xs[0][0];
#pragma unroll
    for (int i = tid; i < ROWS * K / 4; i += 128) xs4[i] = A4[i];
    __syncthreads();

    float acc[ROWS];
#pragma unroll
    for (int r = 0; r < ROWS; r++) acc[r] = 0.0f;

#pragma unroll 4
    for (int k = 0; k < K; k++) {
        float wv = W[k * CH + tid];
#pragma unroll
        for (int r = 0; r < ROWS; r++) acc[r] += xs[r][k] * wv;
    }

    float* Cp = C + (size_t)row0 * CH + tid;
#pragma unroll
    for (int r = 0; r < ROWS; r++) Cp[(size_t)r * CH] = acc[r];
}

// ---------------------------------------------------------------------------
// CSR aggregation: one warp per destination node. No atomics.
// out[i] = b + dinv[i]^2 * h[i] + sum_j norm_j * h[src_j]
// Each lane owns 4 contiguous channels (float4).
// ---------------------------------------------------------------------------
__global__ __launch_bounds__(256) void agg_csr_kernel(const float* __restrict__ h,
                                                      const float* __restrict__ b,
                                                      float* __restrict__ out) {
    int w = (blockIdx.x * blockDim.x + threadIdx.x) >> 5;
    int lane = threadIdx.x & 31;
    if (w >= NNODES) return;
    const float4* h4 = (const float4*)h;

    float di = g_dinv[w];
    float s = di * di;
    float4 hv = h4[(size_t)w * 32 + lane];
    float4 bv = ((const float4*)b)[lane];
    float4 acc;
    acc.x = bv.x + s * hv.x;
    acc.y = bv.y + s * hv.y;
    acc.z = bv.z + s * hv.z;
    acc.w = bv.w + s * hv.w;

    int j = g_rowptr[w];
    int end = g_rowptr[w + 1];
    // 2-wide unroll for ILP on the dependent src->gather chain
    for (; j + 1 < end; j += 2) {
        int s0 = g_csr_src[j];
        int s1 = g_csr_src[j + 1];
        float n0 = g_csr_norm[j];
        float n1 = g_csr_norm[j + 1];
        float4 v0 = h4[(size_t)s0 * 32 + lane];
        float4 v1 = h4[(size_t)s1 * 32 + lane];
        acc.x += n0 * v0.x + n1 * v1.x;
        acc.y += n0 * v0.y + n1 * v1.y;
        acc.z += n0 * v0.z + n1 * v1.z;
        acc.w += n0 * v0.w + n1 * v1.w;
    }
    if (j < end) {
        int s0 = g_csr_src[j];
        float n0 = g_csr_norm[j];
        float4 v0 = h4[(size_t)s0 * 32 + lane];
        acc.x += n0 * v0.x;
        acc.y += n0 * v0.y;
        acc.z += n0 * v0.z;
        acc.w += n0 * v0.w;
    }
    ((float4*)out)[(size_t)w * 32 + lane] = acc;
}

// ---------------------------------------------------------------------------
// BatchNorm stats
// ---------------------------------------------------------------------------
__global__ void zero_stats_kernel() {
    if (threadIdx.x < 2 * CH) g_stats[threadIdx.x] = 0.0f;
}

__global__ __launch_bounds__(128) void bn_stats_kernel(const float* __restrict__ h) {
    int c = threadIdx.x;
    int row0 = blockIdx.x * 128;
    int rend = min(row0 + 128, NNODES);
    float s = 0.0f, s2 = 0.0f;
    for (int r = row0; r < rend; r++) {
        float v = h[(size_t)r * CH + c];
        s += v;
        s2 += v * v;
    }
    atomicAdd(&g_stats[c], s);
    atomicAdd(&g_stats[CH + c], s2);
}

// ---------------------------------------------------------------------------
// BN apply + ReLU (in place)
// ---------------------------------------------------------------------------
__global__ __launch_bounds__(256) void bn_apply_kernel(float* __restrict__ h,
                                                       const float* __restrict__ gamma,
                                                       const float* __restrict__ beta) {
    __shared__ float sc[CH], sh[CH];
    if (threadIdx.x < CH) {
        float mean = g_stats[threadIdx.x] * (1.0f / NNODES);
        float var = g_stats[CH + threadIdx.x] * (1.0f / NNODES) - mean * mean;
        float scale = gamma[threadIdx.x] * rsqrtf(var + 1e-5f);
        sc[threadIdx.x] = scale;
        sh[threadIdx.x] = beta[threadIdx.x] - mean * scale;
    }
    __syncthreads();
    const int total = NNODES * CH / 4;
    for (int idx = blockIdx.x * blockDim.x + threadIdx.x; idx < total;
         idx += gridDim.x * blockDim.x) {
        float4 v = ((float4*)h)[idx];
        int c4 = (idx & 31) * 4;
        v.x = fmaxf(v.x * sc[c4 + 0] + sh[c4 + 0], 0.0f);
        v.y = fmaxf(v.y * sc[c4 + 1] + sh[c4 + 1], 0.0f);
        v.z = fmaxf(v.z * sc[c4 + 2] + sh[c4 + 2], 0.0f);
        v.w = fmaxf(v.w * sc[c4 + 3] + sh[c4 + 3], 0.0f);
        ((float4*)h)[idx] = v;
    }
}

// ---------------------------------------------------------------------------
// Final fused layer: out = [h | relu(dist*Wd+bd) | relu(deg*Wg+bg)] @ Wm + bm
// ---------------------------------------------------------------------------
__global__ __launch_bounds__(128) void final_kernel(const float* __restrict__ h,
                                                    const float* __restrict__ dist,
                                                    const float* __restrict__ degf,
                                                    const float* __restrict__ Wd,
                                                    const float* __restrict__ bd,
                                                    const float* __restrict__ Wg,
                                                    const float* __restrict__ bg,
                                                    const float* __restrict__ Wm,
                                                    const float* __restrict__ bm,
                                                    float* __restrict__ out) {
    __shared__ float hs[ROWS][CH];
    __shared__ float dfs[ROWS][CH];
    __shared__ float gfs[ROWS][CH];
    const int row0 = blockIdx.x * ROWS;
    const int tid = threadIdx.x;

    const float4* h4 = (const float4*)(h + (size_t)row0 * CH);
#pragma unroll
    for (int i = tid; i < ROWS * CH / 4; i += 128) ((float4*)&hs[0][0])[i] = h4[i];

    float wd = Wd[tid], bdv = bd[tid], wg = Wg[tid], bgv = bg[tid];
#pragma unroll
    for (int r = 0; r < ROWS; r++) {
        dfs[r][tid] = fmaxf(dist[row0 + r] * wd + bdv, 0.0f);
        gfs[r][tid] = fmaxf(degf[row0 + r] * wg + bgv, 0.0f);
    }
    __syncthreads();

    float acc[ROWS];
    float bmv = bm[tid];
#pragma unroll
    for (int r = 0; r < ROWS; r++) acc[r] = bmv;

#pragma unroll 2
    for (int j = 0; j < CH; j++) {
        float w1 = Wm[(size_t)j * CH + tid];
        float w2 = Wm[(size_t)(CH + j) * CH + tid];
        float w3 = Wm[(size_t)(2 * CH + j) * CH + tid];
#pragma unroll
        for (int r = 0; r < ROWS; r++)
            acc[r] += hs[r][j] * w1 + dfs[r][j] * w2 + gfs[r][j] * w3;
    }

    float* op = out + (size_t)row0 * CH + tid;
#pragma unroll
    for (int r = 0; r < ROWS; r++) op[(size_t)r * CH] = acc[r];
}

// ---------------------------------------------------------------------------
extern "C" void kernel_launch(void* const* d_in, const int* in_sizes, int n_in,
                              void* d_out, int out_size) {
    const float* x     = (const float*)d_in[0];
    const void*  ei    = d_in[1];
    const float* ew    = (const float*)d_in[2];
    const float* dist  = (const float*)d_in[3];
    const float* degf  = (const float*)d_in[4];
    const float* W1    = (const float*)d_in[5];
    const float* b1    = (const float*)d_in[6];
    const float* W2    = (const float*)d_in[7];
    const float* b2    = (const float*)d_in[8];
    const float* g1    = (const float*)d_in[9];
    const float* be1   = (const float*)d_in[10];
    const float* g2    = (const float*)d_in[11];
    const float* be2   = (const float*)d_in[12];
    const float* Wd    = (const float*)d_in[13];
    const float* bd    = (const float*)d_in[14];
    const float* Wg    = (const float*)d_in[15];
    const float* bg    = (const float*)d_in[16];
    const float* Wm    = (const float*)d_in[17];
    const float* bm    = (const float*)d_in[18];
    float* out = (float*)d_out;

    float *bufA, *bufB;
    cudaGetSymbolAddress((void**)&bufA, g_bufA);
    cudaGetSymbolAddress((void**)&bufB, g_bufB);

    const int nodeBlocks = (NNODES + 255) / 256;
    const int edgeBlocks = (NEDGES + 255) / 256;
    const int rowBlocks  = NNODES / ROWS;              // 3125 exact
    const int aggBlocks  = (NNODES * 32 + 255) / 256;  // warp per node

    // --- gcn_norm + CSR build ---
    detect_idx_kernel<<<1, 256>>>((const int*)ei);
    deg_init_kernel<<<nodeBlocks, 256>>>();
    deg_count_kernel<<<edgeBlocks, 256>>>(ei, ew);
    deg_finalize_kernel<<<nodeBlocks, 256>>>();
    scan_kernel<<<1, SCAN_T>>>();
    fill_kernel<<<edgeBlocks, 256>>>(ei, ew);

    // --- layer 1: conv + BN + ReLU ---
    gemm_kernel<CIN><<<rowBlocks, 128>>>(x, W1, bufA);
    agg_csr_kernel<<<aggBlocks, 256>>>(bufA, b1, bufB);
    zero_stats_kernel<<<1, 256>>>();
    bn_stats_kernel<<<(NNODES + 127) / 128, 128>>>(bufB);
    bn_apply_kernel<<<2048, 256>>>(bufB, g1, be1);

    // --- layer 2: conv + BN + ReLU ---
    gemm_kernel<CH><<<rowBlocks, 128>>>(bufB, W2, bufA);
    agg_csr_kernel<<<aggBlocks, 256>>>(bufA, b2, bufB);
    zero_stats_kernel<<<1, 256>>>();
    bn_stats_kernel<<<(NNODES + 127) / 128, 128>>>(bufB);
    bn_apply_kernel<<<2048, 256>>>(bufB, g2, be2);

    // --- final fused projection ---
    final_kernel<<<rowBlocks, 128>>>(bufB, dist, degf, Wd, bd, Wg, bg, Wm, bm, out);
}

// round 3
// speedup vs baseline: 1.8140x; 1.1539x over previous
#include <cuda_runtime.h>
#include <math.h>

// Problem-fixed dimensions
#define NNODES 100000
#define NEDGES 1600000
#define CIN 64
#define CH 128
#define ROWS 32          // rows per block in GEMM kernels (100000/32 exact)
#define KFIN 384         // final projection K

// Scratch (__device__ globals; no allocation allowed)
__device__ __align__(128) float g_bufA[(size_t)NNODES * CH];
__device__ __align__(128) float g_bufB[(size_t)NNODES * CH];
__device__ __align__(128) float g_dinv[NNODES];
__device__ __align__(128) float g_stats[4 * CH];       // [sum1|sq1|sum2|sq2]
__device__ __align__(128) int   g_rowptr[NNODES + 1];
__device__ __align__(128) int   g_cursor[NNODES];
__device__ __align__(128) int   g_csr_src[NEDGES];
__device__ __align__(128) float g_csr_norm[NEDGES];
__device__ __align__(128) float g_Wp1[CIN * CH];       // k-packed weights
__device__ __align__(128) float g_Wp2[CH * CH];
__device__ __align__(128) float g_Wpm[KFIN * CH];
__device__ int g_idx32;

// ---------------------------------------------------------------------------
// f32x2 packed-math helpers
// ---------------------------------------------------------------------------
typedef unsigned long long ull;

__device__ __forceinline__ ull ffma2(ull a, ull b, ull c) {
    ull d;
    asm("fma.rn.f32x2 %0, %1, %2, %3;" : "=l"(d) : "l"(a), "l"(b), "l"(c));
    return d;
}
__device__ __forceinline__ float unpack_sum(ull a) {
    float lo, hi;
    asm("mov.b64 {%0, %1}, %2;" : "=f"(lo), "=f"(hi) : "l"(a));
    return lo + hi;
}

// ---------------------------------------------------------------------------
// Detect edge_index dtype (int64 values < 2^31 -> odd 32-bit words zero)
// ---------------------------------------------------------------------------
__global__ void detect_idx_kernel(const int* __restrict__ ei) {
    __shared__ int s_any;
    if (threadIdx.x == 0) s_any = 0;
    __syncthreads();
    int any = 0;
    for (int i = 1 + 2 * threadIdx.x; i < 4096; i += 2 * blockDim.x) any |= ei[i];
    if (any) atomicOr(&s_any, 1);
    __syncthreads();
    if (threadIdx.x == 0) g_idx32 = (s_any != 0) ? 1 : 0;
}

__device__ __forceinline__ void load_edge(const void* ei, int e, int& src, int& dst) {
    if (g_idx32) {
        const int* p = (const int*)ei;
        src = p[e];
        dst = p[NEDGES + e];
    } else {
        const long long* p = (const long long*)ei;
        src = (int)p[e];
        dst = (int)p[NEDGES + e];
    }
}

// ---------------------------------------------------------------------------
// Init: dinv=1, counts=0, stats=0
// ---------------------------------------------------------------------------
__global__ void deg_init_kernel() {
    int i = blockIdx.x * blockDim.x + threadIdx.x;
    if (i < NNODES) {
        g_dinv[i] = 1.0f;
        g_cursor[i] = 0;
    }
    if (i < 4 * CH) g_stats[i] = 0.0f;
}

__global__ void deg_count_kernel(const void* __restrict__ ei,
                                 const float* __restrict__ ew) {
    int e = blockIdx.x * blockDim.x + threadIdx.x;
    if (e >= NEDGES) return;
    int src, dst;
    load_edge(ei, e, src, dst);
    atomicAdd(&g_dinv[dst], ew[e]);
    atomicAdd(&g_cursor[dst], 1);
}

// ---------------------------------------------------------------------------
// Single-block scan of counts -> rowptr (+cursor copy) + dinv = rsqrt(deg)
// ---------------------------------------------------------------------------
#define SCAN_T 1024
__global__ __launch_bounds__(SCAN_T) void scan_kernel() {
    __shared__ int ssum[SCAN_T];
    const int CHUNK = (NNODES + SCAN_T - 1) / SCAN_T;
    int t = threadIdx.x;
    int start = t * CHUNK;
    int end = min(start + CHUNK, NNODES);
    int s = 0;
    for (int i = start; i < end; i++) {
        s += g_cursor[i];
        g_dinv[i] = rsqrtf(g_dinv[i]);
    }
    ssum[t] = s;
    __syncthreads();
    for (int off = 1; off < SCAN_T; off <<= 1) {
        int v = (t >= off) ? ssum[t - off] : 0;
        __syncthreads();
        ssum[t] += v;
        __syncthreads();
    }
    int run = (t == 0) ? 0 : ssum[t - 1];
    for (int i = start; i < end; i++) {
        int c = g_cursor[i];
        g_rowptr[i] = run;
        g_cursor[i] = run;
        run += c;
    }
    if (t == SCAN_T - 1) g_rowptr[NNODES] = run;
}

__global__ void fill_kernel(const void* __restrict__ ei,
                            const float* __restrict__ ew) {
    int e = blockIdx.x * blockDim.x + threadIdx.x;
    if (e >= NEDGES) return;
    int src, dst;
    load_edge(ei, e, src, dst);
    float norm = g_dinv[src] * ew[e] * g_dinv[dst];
    int pos = atomicAdd(&g_cursor[dst], 1);
    g_csr_src[pos] = src;
    g_csr_norm[pos] = norm;
}

// ---------------------------------------------------------------------------
// Pack weights: Wp[kp2][c] = (W[4kp2][c], W[4kp2+1][c], W[4kp2+2][c], W[4kp2+3][c])
// All three weight matrices in one grid-stride launch.
// ---------------------------------------------------------------------------
__global__ void pack_kernel(const float* __restrict__ W1,
                            const float* __restrict__ W2,
                            const float* __restrict__ Wm) {
    const int n1 = (CIN / 4) * CH;   // 2048 float4s
    const int n2 = (CH / 4) * CH;    // 4096
    const int n3 = (KFIN / 4) * CH;  // 12288
    for (int idx = blockIdx.x * blockDim.x + threadIdx.x; idx < n1 + n2 + n3;
         idx += gridDim.x * blockDim.x) {
        const float* W;
        float* Wp;
        int i = idx;
        if (i < n1)      { W = W1; Wp = g_Wp1; }
        else if (i < n1 + n2) { W = W2; Wp = g_Wp2; i -= n1; }
        else             { W = Wm; Wp = g_Wpm; i -= n1 + n2; }
        int kp2 = i / CH, c = i % CH;
        float4 v;
        v.x = W[(4 * kp2 + 0) * CH + c];
        v.y = W[(4 * kp2 + 1) * CH + c];
        v.z = W[(4 * kp2 + 2) * CH + c];
        v.w = W[(4 * kp2 + 3) * CH + c];
        ((float4*)Wp)[i] = v;
    }
}

// ---------------------------------------------------------------------------
// Aggregation of 64-channel input x (layer 1, pre-transform).
// 2 nodes per warp: half-warp (16 lanes) x float4 = 64 channels.
// out[i] = dinv^2 * x[i] + sum norm * x[src]
// ---------------------------------------------------------------------------
__global__ __launch_bounds__(256) void agg64_kernel(const float* __restrict__ x,
                                                    float* __restrict__ out) {
    int warp = (blockIdx.x * blockDim.x + threadIdx.x) >> 5;
    int lane = threadIdx.x & 31;
    int node = warp * 2 + (lane >> 4);
    int l16 = lane & 15;
    if (node >= NNODES) return;
    const float4* x4 = (const float4*)x;

    float di = g_dinv[node];
    float s = di * di;
    float4 hv = x4[(size_t)node * 16 + l16];
    float4 acc = make_float4(s * hv.x, s * hv.y, s * hv.z, s * hv.w);

    int j = g_rowptr[node];
    int end = g_rowptr[node + 1];
    for (; j + 1 < end; j += 2) {
        int s0 = g_csr_src[j], s1 = g_csr_src[j + 1];
        float n0 = g_csr_norm[j], n1 = g_csr_norm[j + 1];
        float4 v0 = x4[(size_t)s0 * 16 + l16];
        float4 v1 = x4[(size_t)s1 * 16 + l16];
        acc.x += n0 * v0.x + n1 * v1.x;
        acc.y += n0 * v0.y + n1 * v1.y;
        acc.z += n0 * v0.z + n1 * v1.z;
        acc.w += n0 * v0.w + n1 * v1.w;
    }
    if (j < end) {
        int s0 = g_csr_src[j];
        float n0 = g_csr_norm[j];
        float4 v0 = x4[(size_t)s0 * 16 + l16];
        acc.x += n0 * v0.x;
        acc.y += n0 * v0.y;
        acc.z += n0 * v0.z;
        acc.w += n0 * v0.w;
    }
    ((float4*)out)[(size_t)node * 16 + l16] = acc;
}

// ---------------------------------------------------------------------------
// Aggregation of 128-channel h1 with BN1+ReLU applied on the fly.
// One warp per node, lane owns 4 channels.
// ---------------------------------------------------------------------------
__global__ __launch_bounds__(256) void agg_bn_kernel(const float* __restrict__ h,
                                                     const float* __restrict__ gamma,
                                                     const float* __restrict__ beta,
                                                     float* __restrict__ out) {
    __shared__ float sc[CH], sh[CH];
    if (threadIdx.x < CH) {
        int c = threadIdx.x;
        float mean = g_stats[c] * (1.0f / NNODES);
        float var = g_stats[CH + c] * (1.0f / NNODES) - mean * mean;
        float scale = gamma[c] * rsqrtf(var + 1e-5f);
        sc[c] = scale;
        sh[c] = beta[c] - mean * scale;
    }
    __syncthreads();

    int node = (blockIdx.x * blockDim.x + threadIdx.x) >> 5;
    int lane = threadIdx.x & 31;
    if (node >= NNODES) return;
    const float4* h4 = (const float4*)h;
    float4 scv = *(const float4*)&sc[lane * 4];
    float4 shv = *(const float4*)&sh[lane * 4];

    float di = g_dinv[node];
    float s = di * di;
    float4 hv = h4[(size_t)node * 32 + lane];
    float4 acc;
    acc.x = s * fmaxf(hv.x * scv.x + shv.x, 0.0f);
    acc.y = s * fmaxf(hv.y * scv.y + shv.y, 0.0f);
    acc.z = s * fmaxf(hv.z * scv.z + shv.z, 0.0f);
    acc.w = s * fmaxf(hv.w * scv.w + shv.w, 0.0f);

    int j = g_rowptr[node];
    int end = g_rowptr[node + 1];
    for (; j + 1 < end; j += 2) {
        int s0 = g_csr_src[j], s1 = g_csr_src[j + 1];
        float n0 = g_csr_norm[j], n1 = g_csr_norm[j + 1];
        float4 v0 = h4[(size_t)s0 * 32 + lane];
        float4 v1 = h4[(size_t)s1 * 32 + lane];
        acc.x += n0 * fmaxf(v0.x * scv.x + shv.x, 0.0f) + n1 * fmaxf(v1.x * scv.x + shv.x, 0.0f);
        acc.y += n0 * fmaxf(v0.y * scv.y + shv.y, 0.0f) + n1 * fmaxf(v1.y * scv.y + shv.y, 0.0f);
        acc.z += n0 * fmaxf(v0.z * scv.z + shv.z, 0.0f) + n1 * fmaxf(v1.z * scv.z + shv.z, 0.0f);
        acc.w += n0 * fmaxf(v0.w * scv.w + shv.w, 0.0f) + n1 * fmaxf(v1.w * scv.w + shv.w, 0.0f);
    }
    if (j < end) {
        int s0 = g_csr_src[j];
        float n0 = g_csr_norm[j];
        float4 v0 = h4[(size_t)s0 * 32 + lane];
        acc.x += n0 * fmaxf(v0.x * scv.x + shv.x, 0.0f);
        acc.y += n0 * fmaxf(v0.y * scv.y + shv.y, 0.0f);
        acc.z += n0 * fmaxf(v0.z * scv.z + shv.z, 0.0f);
        acc.w += n0 * fmaxf(v0.w * scv.w + shv.w, 0.0f);
    }
    ((float4*)out)[(size_t)node * 32 + lane] = acc;
}

// ---------------------------------------------------------------------------
// GEMM: C[N x 128] = A[N x K] @ W[K x 128] + b, with BN-stats epilogue.
// f32x2 packed over k-parity; Wp is k-packed. 128 threads, ROWS rows/block.
// ---------------------------------------------------------------------------
template <int K>
__global__ __launch_bounds__(128) void gemm_kernel(const float* __restrict__ A,
                                                   const float* __restrict__ Wp,
                                                   const float* __restrict__ b,
                                                   float* __restrict__ C,
                                                   float* __restrict__ stats) {
    __shared__ float xs[ROWS][K];
    const int row0 = blockIdx.x * ROWS;
    const int tid = threadIdx.x;

    const float4* A4 = (const float4*)(A + (size_t)row0 * K);
    float4* xs4 = (float4*)&xs[0][0];
#pragma unroll
    for (int i = tid; i < ROWS * K / 4; i += 128) xs4[i] = A4[i];
    __syncthreads();

    ull acc[ROWS];
#pragma unroll
    for (int r = 0; r < ROWS; r++) acc[r] = 0ULL;

    const ulonglong2* Wp2 = (const ulonglong2*)Wp;
#pragma unroll 2
    for (int kp2 = 0; kp2 < K / 4; kp2++) {
        ulonglong2 w = Wp2[kp2 * CH + tid];
        const ulonglong2* xrow = (const ulonglong2*)&xs[0][4 * kp2];
#pragma unroll
        for (int r = 0; r < ROWS; r++) {
            ulonglong2 xv = *(const ulonglong2*)((const char*)xrow + (size_t)r * K * 4);
            acc[r] = ffma2(xv.x, w.x, acc[r]);
            acc[r] = ffma2(xv.y, w.y, acc[r]);
        }
    }

    float bias = b[tid];
    float s = 0.0f, s2 = 0.0f;
    float* Cp = C + (size_t)row0 * CH + tid;
#pragma unroll
    for (int r = 0; r < ROWS; r++) {
        float v = unpack_sum(acc[r]) + bias;
        Cp[(size_t)r * CH] = v;
        s += v;
        s2 += v * v;
    }
    atomicAdd(&stats[tid], s);
    atomicAdd(&stats[CH + tid], s2);
}

// ---------------------------------------------------------------------------
// Final fused layer (dynamic smem):
// cs[r][0:128]   = relu(bn2(h2[row0+r]))
// cs[r][128:256] = relu(dist*Wd+bd), cs[r][256:384] = relu(deg*Wg+bg)
// out = cs @ Wm + bm   (f32x2 packed mainloop over K=384)
// ---------------------------------------------------------------------------
__global__ __launch_bounds__(128) void final_kernel(const float* __restrict__ h,
                                                    const float* __restrict__ dist,
                                                    const float* __restrict__ degf,
                                                    const float* __restrict__ Wd,
                                                    const float* __restrict__ bd,
                                                    const float* __restrict__ Wg,
                                                    const float* __restrict__ bg,
                                                    const float* __restrict__ Wp,
                                                    const float* __restrict__ bm,
                                                    const float* __restrict__ gamma,
                                                    const float* __restrict__ beta,
                                                    float* __restrict__ out) {
    extern __shared__ float smem[];
    float* cs = smem;                       // [ROWS][KFIN]
    float* sc = smem + ROWS * KFIN;         // [CH]
    float* sh = sc + CH;                    // [CH]
    const int row0 = blockIdx.x * ROWS;
    const int tid = threadIdx.x;

    if (tid < CH) {
        float mean = g_stats[2 * CH + tid] * (1.0f / NNODES);
        float var = g_stats[3 * CH + tid] * (1.0f / NNODES) - mean * mean;
        float scale = gamma[tid] * rsqrtf(var + 1e-5f);
        sc[tid] = scale;
        sh[tid] = beta[tid] - mean * scale;
    }
    __syncthreads();

    // h2 with BN+ReLU into cs[r][0:128]
    const float4* h4 = (const float4*)(h + (size_t)row0 * CH);
#pragma unroll
    for (int i = tid; i < ROWS * CH / 4; i += 128) {
        int r = i >> 5;
        int c = (i & 31) * 4;
        float4 v = h4[i];
        float4 scv = *(const float4*)&sc[c];
        float4 shv = *(const float4*)&sh[c];
        v.x = fmaxf(v.x * scv.x + shv.x, 0.0f);
        v.y = fmaxf(v.y * scv.y + shv.y, 0.0f);
        v.z = fmaxf(v.z * scv.z + shv.z, 0.0f);
        v.w = fmaxf(v.w * scv.w + shv.w, 0.0f);
        *(float4*)&cs[r * KFIN + c] = v;
    }
    float wd = Wd[tid], bdv = bd[tid], wg = Wg[tid], bgv = bg[tid];
#pragma unroll
    for (int r = 0; r < ROWS; r++) {
        cs[r * KFIN + CH + tid] = fmaxf(dist[row0 + r] * wd + bdv, 0.0f);
        cs[r * KFIN + 2 * CH + tid] = fmaxf(degf[row0 + r] * wg + bgv, 0.0f);
    }
    __syncthreads();

    ull acc[ROWS];
#pragma unroll
    for (int r = 0; r < ROWS; r++) acc[r] = 0ULL;

    const ulonglong2* Wp2 = (const ulonglong2*)Wp;
#pragma unroll 2
    for (int kp2 = 0; kp2 < KFIN / 4; kp2++) {
        ulonglong2 w = Wp2[kp2 * CH + tid];
        const char* xbase = (const char*)&cs[4 * kp2];
#pragma unroll
        for (int r = 0; r < ROWS; r++) {
            ulonglong2 xv = *(const ulonglong2*)(xbase + (size_t)r * KFIN * 4);
            acc[r] = ffma2(xv.x, w.x, acc[r]);
            acc[r] = ffma2(xv.y, w.y, acc[r]);
        }
    }

    float bias = bm[tid];
    float* op = out + (size_t)row0 * CH + tid;
#pragma unroll
    for (int r = 0; r < ROWS; r++) op[(size_t)r * CH] = unpack_sum(acc[r]) + bias;
}

// ---------------------------------------------------------------------------
extern "C" void kernel_launch(void* const* d_in, const int* in_sizes, int n_in,
                              void* d_out, int out_size) {
    const float* x     = (const float*)d_in[0];
    const void*  ei    = d_in[1];
    const float* ew    = (const float*)d_in[2];
    const float* dist  = (const float*)d_in[3];
    const float* degf  = (const float*)d_in[4];
    const float* W1    = (const float*)d_in[5];
    const float* b1    = (const float*)d_in[6];
    const float* W2    = (const float*)d_in[7];
    const float* b2    = (const float*)d_in[8];
    const float* g1    = (const float*)d_in[9];
    const float* be1   = (const float*)d_in[10];
    const float* g2    = (const float*)d_in[11];
    const float* be2   = (const float*)d_in[12];
    const float* Wd    = (const float*)d_in[13];
    const float* bd    = (const float*)d_in[14];
    const float* Wg    = (const float*)d_in[15];
    const float* bg    = (const float*)d_in[16];
    const float* Wm    = (const float*)d_in[17];
    const float* bm    = (const float*)d_in[18];
    float* out = (float*)d_out;

    float *bufA, *bufB, *stats, *Wp1, *Wp2, *Wpm;
    cudaGetSymbolAddress((void**)&bufA, g_bufA);
    cudaGetSymbolAddress((void**)&bufB, g_bufB);
    cudaGetSymbolAddress((void**)&stats, g_stats);
    cudaGetSymbolAddress((void**)&Wp1, g_Wp1);
    cudaGetSymbolAddress((void**)&Wp2, g_Wp2);
    cudaGetSymbolAddress((void**)&Wpm, g_Wpm);

    const int nodeBlocks = (NNODES + 255) / 256;
    const int edgeBlocks = (NEDGES + 255) / 256;
    const int rowBlocks  = NNODES / ROWS;                  // 3125
    const int agg128Blocks = (NNODES * 32 + 255) / 256;
    const int agg64Blocks  = ((NNODES + 1) / 2 * 32 + 255) / 256;
    const int FIN_SMEM = (ROWS * KFIN + 2 * CH) * 4;       // 50176 B

    static int smem_set = 0;
    cudaFuncSetAttribute(final_kernel, cudaFuncAttributeMaxDynamicSharedMemorySize, FIN_SMEM);
    (void)smem_set;

    // --- gcn_norm + CSR build + weight packing ---
    detect_idx_kernel<<<1, 256>>>((const int*)ei);
    deg_init_kernel<<<nodeBlocks, 256>>>();
    pack_kernel<<<160, 256>>>(W1, W2, Wm);
    deg_count_kernel<<<edgeBlocks, 256>>>(ei, ew);
    scan_kernel<<<1, SCAN_T>>>();
    fill_kernel<<<edgeBlocks, 256>>>(ei, ew);

    // --- layer 1: aggregate(x) -> GEMM(+stats1) ---
    agg64_kernel<<<agg64Blocks, 256>>>(x, bufA);
    gemm_kernel<CIN><<<rowBlocks, 128>>>(bufA, Wp1, b1, bufB, stats);

    // --- layer 2: aggregate(bn1(h1)) -> GEMM(+stats2) ---
    agg_bn_kernel<<<agg128Blocks, 256>>>(bufB, g1, be1, bufA);
    gemm_kernel<CH><<<rowBlocks, 128>>>(bufA, Wp2, b2, bufB, stats + 2 * CH);

    // --- final: bn2 + feature MLPs + 384x128 projection ---
    final_kernel<<<rowBlocks, 128, FIN_SMEM>>>(bufB, dist, degf, Wd, bd, Wg, bg,
                                               Wpm, bm, g2, be2, out);
}

// round 4
// speedup vs baseline: 2.1049x; 1.1604x over previous
#include <cuda_runtime.h>
#include <math.h>

// Problem-fixed dimensions
#define NNODES 100000
#define NEDGES 1600000
#define CIN 64
#define CH 128
#define ROWS 32          // rows per block in GEMM kernels
#define KFIN 384         // final projection K

// Scratch (__device__ globals; no allocation allowed)
__device__ __align__(128) float g_bufA[(size_t)NNODES * CH];
__device__ __align__(128) float g_bufB[(size_t)NNODES * CH];
__device__ __align__(128) float g_dinv[NNODES];
__device__ __align__(128) float g_stats[4 * CH];       // [sum1|sq1|sum2|sq2]
__device__ __align__(128) int   g_rowptr[NNODES + 1];
__device__ __align__(128) int   g_cursor[NNODES];
__device__ __align__(128) int   g_csr_src[NEDGES];
__device__ __align__(128) float g_csr_norm[NEDGES];
__device__ __align__(128) float g_Wp1[CIN * CH];       // k-packed weights
__device__ __align__(128) float g_Wp2[CH * CH];
__device__ __align__(128) float g_Wpm[KFIN * CH];
__device__ __align__(128) int   g_part[256];           // scan partials
__device__ int g_idx32;

#define SCAN_BLOCKS 196
#define SCAN_BT 512

// ---------------------------------------------------------------------------
typedef unsigned long long ull;

__device__ __forceinline__ ull ffma2(ull a, ull b, ull c) {
    ull d;
    asm("fma.rn.f32x2 %0, %1, %2, %3;" : "=l"(d) : "l"(a), "l"(b), "l"(c));
    return d;
}
__device__ __forceinline__ float unpack_sum(ull a) {
    float lo, hi;
    asm("mov.b64 {%0, %1}, %2;" : "=f"(lo), "=f"(hi) : "l"(a));
    return lo + hi;
}

// ---------------------------------------------------------------------------
__global__ void detect_idx_kernel(const int* __restrict__ ei) {
    __shared__ int s_any;
    if (threadIdx.x == 0) s_any = 0;
    __syncthreads();
    int any = 0;
    for (int i = 1 + 2 * threadIdx.x; i < 4096; i += 2 * blockDim.x) any |= ei[i];
    if (any) atomicOr(&s_any, 1);
    __syncthreads();
    if (threadIdx.x == 0) g_idx32 = (s_any != 0) ? 1 : 0;
}

__device__ __forceinline__ void load_edge(const void* ei, int e, int& src, int& dst) {
    if (g_idx32) {
        const int* p = (const int*)ei;
        src = p[e];
        dst = p[NEDGES + e];
    } else {
        const long long* p = (const long long*)ei;
        src = (int)p[e];
        dst = (int)p[NEDGES + e];
    }
}

__global__ void deg_init_kernel() {
    int i = blockIdx.x * blockDim.x + threadIdx.x;
    if (i < NNODES) {
        g_dinv[i] = 1.0f;
        g_cursor[i] = 0;
    }
    if (i < 4 * CH) g_stats[i] = 0.0f;
}

__global__ void deg_count_kernel(const void* __restrict__ ei,
                                 const float* __restrict__ ew) {
    int e = blockIdx.x * blockDim.x + threadIdx.x;
    if (e >= NEDGES) return;
    int src, dst;
    load_edge(ei, e, src, dst);
    atomicAdd(&g_dinv[dst], ew[e]);
    atomicAdd(&g_cursor[dst], 1);
}

// ---------------------------------------------------------------------------
// 3-phase multi-block scan of counts -> rowptr/cursor; also dinv = rsqrt(deg).
// ---------------------------------------------------------------------------
__global__ __launch_bounds__(SCAN_BT) void scanA_kernel() {
    __shared__ int ssum[SCAN_BT];
    int i = blockIdx.x * SCAN_BT + threadIdx.x;
    int c = (i < NNODES) ? g_cursor[i] : 0;
    if (i < NNODES) g_dinv[i] = rsqrtf(g_dinv[i]);
    ssum[threadIdx.x] = c;
    __syncthreads();
    for (int off = 1; off < SCAN_BT; off <<= 1) {
        int v = (threadIdx.x >= off) ? ssum[threadIdx.x - off] : 0;
        __syncthreads();
        ssum[threadIdx.x] += v;
        __syncthreads();
    }
    if (i < NNODES) g_rowptr[i] = ssum[threadIdx.x];   // inclusive, no block offset
    if (threadIdx.x == SCAN_BT - 1) g_part[blockIdx.x] = ssum[threadIdx.x];
}

__global__ __launch_bounds__(256) void scanB_kernel() {
    __shared__ int ssum[256];
    int t = threadIdx.x;
    ssum[t] = (t < SCAN_BLOCKS) ? g_part[t] : 0;
    __syncthreads();
    for (int off = 1; off < 256; off <<= 1) {
        int v = (t >= off) ? ssum[t - off] : 0;
        __syncthreads();
        ssum[t] += v;
        __syncthreads();
    }
    // exclusive offsets
    g_part[t] = (t == 0) ? 0 : ssum[t - 1];
    if (t == 255) g_rowptr[NNODES] = ssum[255];   // total (= NEDGES)
}

__global__ __launch_bounds__(SCAN_BT) void scanC_kernel() {
    int i = blockIdx.x * SCAN_BT + threadIdx.x;
    if (i >= NNODES) return;
    int off = g_part[blockIdx.x];
    int excl = g_rowptr[i] + off - g_cursor[i];
    g_rowptr[i] = excl;
    g_cursor[i] = excl;
}

__global__ void fill_kernel(const void* __restrict__ ei,
                            const float* __restrict__ ew) {
    int e = blockIdx.x * blockDim.x + threadIdx.x;
    if (e >= NEDGES) return;
    int src, dst;
    load_edge(ei, e, src, dst);
    float norm = g_dinv[src] * ew[e] * g_dinv[dst];
    int pos = atomicAdd(&g_cursor[dst], 1);
    g_csr_src[pos] = src;
    g_csr_norm[pos] = norm;
}

// ---------------------------------------------------------------------------
__global__ void pack_kernel(const float* __restrict__ W1,
                            const float* __restrict__ W2,
                            const float* __restrict__ Wm) {
    const int n1 = (CIN / 4) * CH;
    const int n2 = (CH / 4) * CH;
    const int n3 = (KFIN / 4) * CH;
    for (int idx = blockIdx.x * blockDim.x + threadIdx.x; idx < n1 + n2 + n3;
         idx += gridDim.x * blockDim.x) {
        const float* W;
        float* Wp;
        int i = idx;
        if (i < n1)      { W = W1; Wp = g_Wp1; }
        else if (i < n1 + n2) { W = W2; Wp = g_Wp2; i -= n1; }
        else             { W = Wm; Wp = g_Wpm; i -= n1 + n2; }
        int kp2 = i / CH, c = i % CH;
        float4 v;
        v.x = W[(4 * kp2 + 0) * CH + c];
        v.y = W[(4 * kp2 + 1) * CH + c];
        v.z = W[(4 * kp2 + 2) * CH + c];
        v.w = W[(4 * kp2 + 3) * CH + c];
        ((float4*)Wp)[i] = v;
    }
}

// ---------------------------------------------------------------------------
// Aggregation of 64-channel x (layer 1, pre-transform). 2 nodes/warp.
// 4-wide unrolled gather for MLP.
// ---------------------------------------------------------------------------
__global__ __launch_bounds__(256) void agg64_kernel(const float* __restrict__ x,
                                                    float* __restrict__ out) {
    int warp = (blockIdx.x * blockDim.x + threadIdx.x) >> 5;
    int lane = threadIdx.x & 31;
    int node = warp * 2 + (lane >> 4);
    int l16 = lane & 15;
    if (node >= NNODES) return;
    const float4* x4 = (const float4*)x;

    float di = g_dinv[node];
    float s = di * di;
    float4 hv = x4[(size_t)node * 16 + l16];
    float4 acc = make_float4(s * hv.x, s * hv.y, s * hv.z, s * hv.w);

    int j = g_rowptr[node];
    int end = g_rowptr[node + 1];
    for (; j + 3 < end; j += 4) {
        int s0 = g_csr_src[j], s1 = g_csr_src[j + 1];
        int s2 = g_csr_src[j + 2], s3 = g_csr_src[j + 3];
        float n0 = g_csr_norm[j], n1 = g_csr_norm[j + 1];
        float n2 = g_csr_norm[j + 2], n3 = g_csr_norm[j + 3];
        float4 v0 = x4[(size_t)s0 * 16 + l16];
        float4 v1 = x4[(size_t)s1 * 16 + l16];
        float4 v2 = x4[(size_t)s2 * 16 + l16];
        float4 v3 = x4[(size_t)s3 * 16 + l16];
        acc.x += n0 * v0.x + n1 * v1.x + n2 * v2.x + n3 * v3.x;
        acc.y += n0 * v0.y + n1 * v1.y + n2 * v2.y + n3 * v3.y;
        acc.z += n0 * v0.z + n1 * v1.z + n2 * v2.z + n3 * v3.z;
        acc.w += n0 * v0.w + n1 * v1.w + n2 * v2.w + n3 * v3.w;
    }
    for (; j < end; j++) {
        int s0 = g_csr_src[j];
        float n0 = g_csr_norm[j];
        float4 v0 = x4[(size_t)s0 * 16 + l16];
        acc.x += n0 * v0.x;
        acc.y += n0 * v0.y;
        acc.z += n0 * v0.z;
        acc.w += n0 * v0.w;
    }
    ((float4*)out)[(size_t)node * 16 + l16] = acc;
}

// ---------------------------------------------------------------------------
// Aggregation of 128-channel h1 with BN1+ReLU on the fly. Warp per node.
// ---------------------------------------------------------------------------
__global__ __launch_bounds__(256) void agg_bn_kernel(const float* __restrict__ h,
                                                     const float* __restrict__ gamma,
                                                     const float* __restrict__ beta,
                                                     float* __restrict__ out) {
    __shared__ float sc[CH], sh[CH];
    if (threadIdx.x < CH) {
        int c = threadIdx.x;
        float mean = g_stats[c] * (1.0f / NNODES);
        float var = g_stats[CH + c] * (1.0f / NNODES) - mean * mean;
        float scale = gamma[c] * rsqrtf(var + 1e-5f);
        sc[c] = scale;
        sh[c] = beta[c] - mean * scale;
    }
    __syncthreads();

    int node = (blockIdx.x * blockDim.x + threadIdx.x) >> 5;
    int lane = threadIdx.x & 31;
    if (node >= NNODES) return;
    const float4* h4 = (const float4*)h;
    float4 scv = *(const float4*)&sc[lane * 4];
    float4 shv = *(const float4*)&sh[lane * 4];

    float di = g_dinv[node];
    float s = di * di;
    float4 hv = h4[(size_t)node * 32 + lane];
    float4 acc;
    acc.x = s * fmaxf(hv.x * scv.x + shv.x, 0.0f);
    acc.y = s * fmaxf(hv.y * scv.y + shv.y, 0.0f);
    acc.z = s * fmaxf(hv.z * scv.z + shv.z, 0.0f);
    acc.w = s * fmaxf(hv.w * scv.w + shv.w, 0.0f);

    int j = g_rowptr[node];
    int end = g_rowptr[node + 1];
    for (; j + 3 < end; j += 4) {
        int s0 = g_csr_src[j], s1 = g_csr_src[j + 1];
        int s2 = g_csr_src[j + 2], s3 = g_csr_src[j + 3];
        float n0 = g_csr_norm[j], n1 = g_csr_norm[j + 1];
        float n2 = g_csr_norm[j + 2], n3 = g_csr_norm[j + 3];
        float4 v0 = h4[(size_t)s0 * 32 + lane];
        float4 v1 = h4[(size_t)s1 * 32 + lane];
        float4 v2 = h4[(size_t)s2 * 32 + lane];
        float4 v3 = h4[(size_t)s3 * 32 + lane];
        acc.x += n0 * fmaxf(v0.x * scv.x + shv.x, 0.0f) + n1 * fmaxf(v1.x * scv.x + shv.x, 0.0f)
               + n2 * fmaxf(v2.x * scv.x + shv.x, 0.0f) + n3 * fmaxf(v3.x * scv.x + shv.x, 0.0f);
        acc.y += n0 * fmaxf(v0.y * scv.y + shv.y, 0.0f) + n1 * fmaxf(v1.y * scv.y + shv.y, 0.0f)
               + n2 * fmaxf(v2.y * scv.y + shv.y, 0.0f) + n3 * fmaxf(v3.y * scv.y + shv.y, 0.0f);
        acc.z += n0 * fmaxf(v0.z * scv.z + shv.z, 0.0f) + n1 * fmaxf(v1.z * scv.z + shv.z, 0.0f)
               + n2 * fmaxf(v2.z * scv.z + shv.z, 0.0f) + n3 * fmaxf(v3.z * scv.z + shv.z, 0.0f);
        acc.w += n0 * fmaxf(v0.w * scv.w + shv.w, 0.0f) + n1 * fmaxf(v1.w * scv.w + shv.w, 0.0f)
               + n2 * fmaxf(v2.w * scv.w + shv.w, 0.0f) + n3 * fmaxf(v3.w * scv.w + shv.w, 0.0f);
    }
    for (; j < end; j++) {
        int s0 = g_csr_src[j];
        float n0 = g_csr_norm[j];
        float4 v0 = h4[(size_t)s0 * 32 + lane];
        acc.x += n0 * fmaxf(v0.x * scv.x + shv.x, 0.0f);
        acc.y += n0 * fmaxf(v0.y * scv.y + shv.y, 0.0f);
        acc.z += n0 * fmaxf(v0.z * scv.z + shv.z, 0.0f);
        acc.w += n0 * fmaxf(v0.w * scv.w + shv.w, 0.0f);
    }
    ((float4*)out)[(size_t)node * 32 + lane] = acc;
}

// ---------------------------------------------------------------------------
// GEMM: C = A @ W + b with BN-stats epilogue (f32x2 packed).
// ---------------------------------------------------------------------------
template <int K>
__global__ __launch_bounds__(128) void gemm_kernel(const float* __restrict__ A,
                                                   const float* __restrict__ Wp,
                                                   const float* __restrict__ b,
                                                   float* __restrict__ C,
                                                   float* __restrict__ stats) {
    __shared__ float xs[ROWS][K];
    const int row0 = blockIdx.x * ROWS;
    const int tid = threadIdx.x;

    const float4* A4 = (const float4*)(A + (size_t)row0 * K);
    float4* xs4 = (float4*)&xs[0][0];
#pragma unroll
    for (int i = tid; i < ROWS * K / 4; i += 128) xs4[i] = A4[i];
    __syncthreads();

    ull acc[ROWS];
#pragma unroll
    for (int r = 0; r < ROWS; r++) acc[r] = 0ULL;

    const ulonglong2* Wp2 = (const ulonglong2*)Wp;
#pragma unroll 2
    for (int kp2 = 0; kp2 < K / 4; kp2++) {
        ulonglong2 w = Wp2[kp2 * CH + tid];
        const ulonglong2* xrow = (const ulonglong2*)&xs[0][4 * kp2];
#pragma unroll
        for (int r = 0; r < ROWS; r++) {
            ulonglong2 xv = *(const ulonglong2*)((const char*)xrow + (size_t)r * K * 4);
            acc[r] = ffma2(xv.x, w.x, acc[r]);
            acc[r] = ffma2(xv.y, w.y, acc[r]);
        }
    }

    float bias = b[tid];
    float s = 0.0f, s2 = 0.0f;
    float* Cp = C + (size_t)row0 * CH + tid;
#pragma unroll
    for (int r = 0; r < ROWS; r++) {
        float v = unpack_sum(acc[r]) + bias;
        Cp[(size_t)r * CH] = v;
        s += v;
        s2 += v * v;
    }
    atomicAdd(&stats[tid], s);
    atomicAdd(&stats[CH + tid], s2);
}

// ---------------------------------------------------------------------------
// Final fused layer (dynamic smem). Also used as a grid-limited ncu probe.
// ---------------------------------------------------------------------------
__global__ __launch_bounds__(128) void final_kernel(const float* __restrict__ h,
                                                    const float* __restrict__ dist,
                                                    const float* __restrict__ degf,
                                                    const float* __restrict__ Wd,
                                                    const float* __restrict__ bd,
                                                    const float* __restrict__ Wg,
                                                    const float* __restrict__ bg,
                                                    const float* __restrict__ Wp,
                                                    const float* __restrict__ bm,
                                                    const float* __restrict__ gamma,
                                                    const float* __restrict__ beta,
                                                    float* __restrict__ out) {
    extern __shared__ float smem[];
    float* cs = smem;                       // [ROWS][KFIN]
    float* sc = smem + ROWS * KFIN;
    float* sh = sc + CH;
    const int row0 = blockIdx.x * ROWS;
    const int tid = threadIdx.x;

    if (tid < CH) {
        float mean = g_stats[2 * CH + tid] * (1.0f / NNODES);
        float var = g_stats[3 * CH + tid] * (1.0f / NNODES) - mean * mean;
        float scale = gamma[tid] * rsqrtf(var + 1e-5f);
        sc[tid] = scale;
        sh[tid] = beta[tid] - mean * scale;
    }
    __syncthreads();

    const float4* h4 = (const float4*)(h + (size_t)row0 * CH);
#pragma unroll
    for (int i = tid; i < ROWS * CH / 4; i += 128) {
        int r = i >> 5;
        int c = (i & 31) * 4;
        float4 v = h4[i];
        float4 scv = *(const float4*)&sc[c];
        float4 shv = *(const float4*)&sh[c];
        v.x = fmaxf(v.x * scv.x + shv.x, 0.0f);
        v.y = fmaxf(v.y * scv.y + shv.y, 0.0f);
        v.z = fmaxf(v.z * scv.z + shv.z, 0.0f);
        v.w = fmaxf(v.w * scv.w + shv.w, 0.0f);
        *(float4*)&cs[r * KFIN + c] = v;
    }
    float wd = Wd[tid], bdv = bd[tid], wg = Wg[tid], bgv = bg[tid];
#pragma unroll
    for (int r = 0; r < ROWS; r++) {
        cs[r * KFIN + CH + tid] = fmaxf(dist[row0 + r] * wd + bdv, 0.0f);
        cs[r * KFIN + 2 * CH + tid] = fmaxf(degf[row0 + r] * wg + bgv, 0.0f);
    }
    __syncthreads();

    ull acc[ROWS];
#pragma unroll
    for (int r = 0; r < ROWS; r++) acc[r] = 0ULL;

    const ulonglong2* Wp2 = (const ulonglong2*)Wp;
#pragma unroll 2
    for (int kp2 = 0; kp2 < KFIN / 4; kp2++) {
        ulonglong2 w = Wp2[kp2 * CH + tid];
        const char* xbase = (const char*)&cs[4 * kp2];
#pragma unroll
        for (int r = 0; r < ROWS; r++) {
            ulonglong2 xv = *(const ulonglong2*)(xbase + (size_t)r * KFIN * 4);
            acc[r] = ffma2(xv.x, w.x, acc[r]);
            acc[r] = ffma2(xv.y, w.y, acc[r]);
        }
    }

    float bias = bm[tid];
    float* op = out + (size_t)row0 * CH + tid;
#pragma unroll
    for (int r = 0; r < ROWS; r++) op[(size_t)r * CH] = unpack_sum(acc[r]) + bias;
}

// ---------------------------------------------------------------------------
extern "C" void kernel_launch(void* const* d_in, const int* in_sizes, int n_in,
                              void* d_out, int out_size) {
    const float* x     = (const float*)d_in[0];
    const void*  ei    = d_in[1];
    const float* ew    = (const float*)d_in[2];
    const float* dist  = (const float*)d_in[3];
    const float* degf  = (const float*)d_in[4];
    const float* W1    = (const float*)d_in[5];
    const float* b1    = (const float*)d_in[6];
    const float* W2    = (const float*)d_in[7];
    const float* b2    = (const float*)d_in[8];
    const float* g1    = (const float*)d_in[9];
    const float* be1   = (const float*)d_in[10];
    const float* g2    = (const float*)d_in[11];
    const float* be2   = (const float*)d_in[12];
    const float* Wd    = (const float*)d_in[13];
    const float* bd    = (const float*)d_in[14];
    const float* Wg    = (const float*)d_in[15];
    const float* bg    = (const float*)d_in[16];
    const float* Wm    = (const float*)d_in[17];
    const float* bm    = (const float*)d_in[18];
    float* out = (float*)d_out;

    float *bufA, *bufB, *stats, *Wp1, *Wp2, *Wpm;
    cudaGetSymbolAddress((void**)&bufA, g_bufA);
    cudaGetSymbolAddress((void**)&bufB, g_bufB);
    cudaGetSymbolAddress((void**)&stats, g_stats);
    cudaGetSymbolAddress((void**)&Wp1, g_Wp1);
    cudaGetSymbolAddress((void**)&Wp2, g_Wp2);
    cudaGetSymbolAddress((void**)&Wpm, g_Wpm);

    const int nodeBlocks = (NNODES + 255) / 256;
    const int edgeBlocks = (NEDGES + 255) / 256;
    const int rowBlocks  = NNODES / ROWS;
    const int agg128Blocks = (NNODES * 32 + 255) / 256;
    const int agg64Blocks  = ((NNODES + 1) / 2 * 32 + 255) / 256;
    const int FIN_SMEM = (ROWS * KFIN + 2 * CH) * 4;

    cudaFuncSetAttribute(final_kernel, cudaFuncAttributeMaxDynamicSharedMemorySize, FIN_SMEM);

    // slots 1-3
    detect_idx_kernel<<<1, 256>>>((const int*)ei);
    deg_init_kernel<<<nodeBlocks, 256>>>();
    pack_kernel<<<160, 256>>>(W1, W2, Wm);

    // slot 4: ncu PROBE of final_kernel (grid-limited; d_out overwritten below)
    final_kernel<<<512, 128, FIN_SMEM>>>(bufB, dist, degf, Wd, bd, Wg, bg,
                                         Wpm, bm, g2, be2, out);

    // --- gcn_norm + CSR build ---
    deg_count_kernel<<<edgeBlocks, 256>>>(ei, ew);
    scanA_kernel<<<SCAN_BLOCKS, SCAN_BT>>>();
    scanB_kernel<<<1, 256>>>();
    scanC_kernel<<<SCAN_BLOCKS, SCAN_BT>>>();
    fill_kernel<<<edgeBlocks, 256>>>(ei, ew);

    // --- layer 1 ---
    agg64_kernel<<<agg64Blocks, 256>>>(x, bufA);
    gemm_kernel<CIN><<<rowBlocks, 128>>>(bufA, Wp1, b1, bufB, stats);

    // --- layer 2 ---
    agg_bn_kernel<<<agg128Blocks, 256>>>(bufB, g1, be1, bufA);
    gemm_kernel<CH><<<rowBlocks, 128>>>(bufA, Wp2, b2, bufB, stats + 2 * CH);

    // --- final ---
    final_kernel<<<rowBlocks, 128, FIN_SMEM>>>(bufB, dist, degf, Wd, bd, Wg, bg,
                                               Wpm, bm, g2, be2, out);
}

// round 5
// speedup vs baseline: 2.4156x; 1.1476x over previous
#include <cuda_runtime.h>
#include <math.h>

// Problem-fixed dimensions
#define NNODES 100000
#define NEDGES 1600000
#define CIN 64
#define CH 128
#define ROWS 32          // rows per block in GEMM kernels
#define KFIN 384         // final projection K

// Scratch (__device__ globals; no allocation allowed)
__device__ __align__(128) float g_bufA[(size_t)NNODES * CH];
__device__ __align__(128) float g_bufB[(size_t)NNODES * CH];
__device__ __align__(128) float g_dinv[NNODES];
__device__ __align__(128) float g_stats[4 * CH];       // [sum1|sq1|sum2|sq2]
__device__ __align__(128) int   g_rowptr[NNODES + 1];
__device__ __align__(128) int   g_cursor[NNODES];
__device__ __align__(128) int   g_csr_src[NEDGES];
__device__ __align__(128) float g_csr_norm[NEDGES];
__device__ __align__(128) float g_Wp1[CIN * CH];       // k-packed weights
__device__ __align__(128) float g_Wp2[CH * CH];
__device__ __align__(128) float g_Wpm[KFIN * CH];
__device__ __align__(128) int   g_part[256];           // scan partials
__device__ int g_idx32;

#define SCAN_BLOCKS 196
#define SCAN_BT 512

// ---------------------------------------------------------------------------
typedef unsigned long long ull;

__device__ __forceinline__ ull ffma2(ull a, ull b, ull c) {
    ull d;
    asm("fma.rn.f32x2 %0, %1, %2, %3;" : "=l"(d) : "l"(a), "l"(b), "l"(c));
    return d;
}
__device__ __forceinline__ float unpack_sum(ull a) {
    float lo, hi;
    asm("mov.b64 {%0, %1}, %2;" : "=f"(lo), "=f"(hi) : "l"(a));
    return lo + hi;
}

// ---------------------------------------------------------------------------
__global__ void detect_idx_kernel(const int* __restrict__ ei) {
    __shared__ int s_any;
    if (threadIdx.x == 0) s_any = 0;
    __syncthreads();
    int any = 0;
    for (int i = 1 + 2 * threadIdx.x; i < 4096; i += 2 * blockDim.x) any |= ei[i];
    if (any) atomicOr(&s_any, 1);
    __syncthreads();
    if (threadIdx.x == 0) g_idx32 = (s_any != 0) ? 1 : 0;
}

__device__ __forceinline__ void load_edge(const void* ei, int e, int& src, int& dst) {
    if (g_idx32) {
        const int* p = (const int*)ei;
        src = p[e];
        dst = p[NEDGES + e];
    } else {
        const long long* p = (const long long*)ei;
        src = (int)p[e];
        dst = (int)p[NEDGES + e];
    }
}

__global__ void deg_init_kernel() {
    int i = blockIdx.x * blockDim.x + threadIdx.x;
    if (i < NNODES) {
        g_dinv[i] = 1.0f;
        g_cursor[i] = 0;
    }
    if (i < 4 * CH) g_stats[i] = 0.0f;
}

__global__ void deg_count_kernel(const void* __restrict__ ei,
                                 const float* __restrict__ ew) {
    int e = blockIdx.x * blockDim.x + threadIdx.x;
    if (e >= NEDGES) return;
    int src, dst;
    load_edge(ei, e, src, dst);
    atomicAdd(&g_dinv[dst], ew[e]);
    atomicAdd(&g_cursor[dst], 1);
}

// ---------------------------------------------------------------------------
// 3-phase multi-block scan of counts -> rowptr/cursor; also dinv = rsqrt(deg).
// ---------------------------------------------------------------------------
__global__ __launch_bounds__(SCAN_BT) void scanA_kernel() {
    __shared__ int ssum[SCAN_BT];
    int i = blockIdx.x * SCAN_BT + threadIdx.x;
    int c = (i < NNODES) ? g_cursor[i] : 0;
    if (i < NNODES) g_dinv[i] = rsqrtf(g_dinv[i]);
    ssum[threadIdx.x] = c;
    __syncthreads();
    for (int off = 1; off < SCAN_BT; off <<= 1) {
        int v = (threadIdx.x >= off) ? ssum[threadIdx.x - off] : 0;
        __syncthreads();
        ssum[threadIdx.x] += v;
        __syncthreads();
    }
    if (i < NNODES) g_rowptr[i] = ssum[threadIdx.x];
    if (threadIdx.x == SCAN_BT - 1) g_part[blockIdx.x] = ssum[threadIdx.x];
}

__global__ __launch_bounds__(256) void scanB_kernel() {
    __shared__ int ssum[256];
    int t = threadIdx.x;
    ssum[t] = (t < SCAN_BLOCKS) ? g_part[t] : 0;
    __syncthreads();
    for (int off = 1; off < 256; off <<= 1) {
        int v = (t >= off) ? ssum[t - off] : 0;
        __syncthreads();
        ssum[t] += v;
        __syncthreads();
    }
    g_part[t] = (t == 0) ? 0 : ssum[t - 1];
    if (t == 255) g_rowptr[NNODES] = ssum[255];
}

__global__ __launch_bounds__(SCAN_BT) void scanC_kernel() {
    int i = blockIdx.x * SCAN_BT + threadIdx.x;
    if (i >= NNODES) return;
    int off = g_part[blockIdx.x];
    int excl = g_rowptr[i] + off - g_cursor[i];
    g_rowptr[i] = excl;
    g_cursor[i] = excl;
}

__global__ void fill_kernel(const void* __restrict__ ei,
                            const float* __restrict__ ew) {
    int e = blockIdx.x * blockDim.x + threadIdx.x;
    if (e >= NEDGES) return;
    int src, dst;
    load_edge(ei, e, src, dst);
    float norm = g_dinv[src] * ew[e] * g_dinv[dst];
    int pos = atomicAdd(&g_cursor[dst], 1);
    g_csr_src[pos] = src;
    g_csr_norm[pos] = norm;
}

// ---------------------------------------------------------------------------
__global__ void pack_kernel(const float* __restrict__ W1,
                            const float* __restrict__ W2,
                            const float* __restrict__ Wm) {
    const int n1 = (CIN / 4) * CH;
    const int n2 = (CH / 4) * CH;
    const int n3 = (KFIN / 4) * CH;
    for (int idx = blockIdx.x * blockDim.x + threadIdx.x; idx < n1 + n2 + n3;
         idx += gridDim.x * blockDim.x) {
        const float* W;
        float* Wp;
        int i = idx;
        if (i < n1)      { W = W1; Wp = g_Wp1; }
        else if (i < n1 + n2) { W = W2; Wp = g_Wp2; i -= n1; }
        else             { W = Wm; Wp = g_Wpm; i -= n1 + n2; }
        int kp2 = i / CH, c = i % CH;
        float4 v;
        v.x = W[(4 * kp2 + 0) * CH + c];
        v.y = W[(4 * kp2 + 1) * CH + c];
        v.z = W[(4 * kp2 + 2) * CH + c];
        v.w = W[(4 * kp2 + 3) * CH + c];
        ((float4*)Wp)[i] = v;
    }
}

// ---------------------------------------------------------------------------
// Aggregation of 64-channel x (layer 1). 2 nodes/warp, 4-wide unroll.
// ---------------------------------------------------------------------------
__global__ __launch_bounds__(256) void agg64_kernel(const float* __restrict__ x,
                                                    float* __restrict__ out) {
    int warp = (blockIdx.x * blockDim.x + threadIdx.x) >> 5;
    int lane = threadIdx.x & 31;
    int node = warp * 2 + (lane >> 4);
    int l16 = lane & 15;
    if (node >= NNODES) return;
    const float4* x4 = (const float4*)x;

    float di = g_dinv[node];
    float s = di * di;
    float4 hv = x4[(size_t)node * 16 + l16];
    float4 acc = make_float4(s * hv.x, s * hv.y, s * hv.z, s * hv.w);

    int j = g_rowptr[node];
    int end = g_rowptr[node + 1];
    for (; j + 3 < end; j += 4) {
        int s0 = g_csr_src[j], s1 = g_csr_src[j + 1];
        int s2 = g_csr_src[j + 2], s3 = g_csr_src[j + 3];
        float n0 = g_csr_norm[j], n1 = g_csr_norm[j + 1];
        float n2 = g_csr_norm[j + 2], n3 = g_csr_norm[j + 3];
        float4 v0 = x4[(size_t)s0 * 16 + l16];
        float4 v1 = x4[(size_t)s1 * 16 + l16];
        float4 v2 = x4[(size_t)s2 * 16 + l16];
        float4 v3 = x4[(size_t)s3 * 16 + l16];
        acc.x += n0 * v0.x + n1 * v1.x + n2 * v2.x + n3 * v3.x;
        acc.y += n0 * v0.y + n1 * v1.y + n2 * v2.y + n3 * v3.y;
        acc.z += n0 * v0.z + n1 * v1.z + n2 * v2.z + n3 * v3.z;
        acc.w += n0 * v0.w + n1 * v1.w + n2 * v2.w + n3 * v3.w;
    }
    for (; j < end; j++) {
        int s0 = g_csr_src[j];
        float n0 = g_csr_norm[j];
        float4 v0 = x4[(size_t)s0 * 16 + l16];
        acc.x += n0 * v0.x;
        acc.y += n0 * v0.y;
        acc.z += n0 * v0.z;
        acc.w += n0 * v0.w;
    }
    ((float4*)out)[(size_t)node * 16 + l16] = acc;
}

// ---------------------------------------------------------------------------
// Aggregation of 128-channel h1 with BN1+ReLU on the fly. Warp per node.
// ---------------------------------------------------------------------------
__global__ __launch_bounds__(256) void agg_bn_kernel(const float* __restrict__ h,
                                                     const float* __restrict__ gamma,
                                                     const float* __restrict__ beta,
                                                     float* __restrict__ out) {
    __shared__ float sc[CH], sh[CH];
    if (threadIdx.x < CH) {
        int c = threadIdx.x;
        float mean = g_stats[c] * (1.0f / NNODES);
        float var = g_stats[CH + c] * (1.0f / NNODES) - mean * mean;
        float scale = gamma[c] * rsqrtf(var + 1e-5f);
        sc[c] = scale;
        sh[c] = beta[c] - mean * scale;
    }
    __syncthreads();

    int node = (blockIdx.x * blockDim.x + threadIdx.x) >> 5;
    int lane = threadIdx.x & 31;
    if (node >= NNODES) return;
    const float4* h4 = (const float4*)h;
    float4 scv = *(const float4*)&sc[lane * 4];
    float4 shv = *(const float4*)&sh[lane * 4];

    float di = g_dinv[node];
    float s = di * di;
    float4 hv = h4[(size_t)node * 32 + lane];
    float4 acc;
    acc.x = s * fmaxf(hv.x * scv.x + shv.x, 0.0f);
    acc.y = s * fmaxf(hv.y * scv.y + shv.y, 0.0f);
    acc.z = s * fmaxf(hv.z * scv.z + shv.z, 0.0f);
    acc.w = s * fmaxf(hv.w * scv.w + shv.w, 0.0f);

    int j = g_rowptr[node];
    int end = g_rowptr[node + 1];
    for (; j + 3 < end; j += 4) {
        int s0 = g_csr_src[j], s1 = g_csr_src[j + 1];
        int s2 = g_csr_src[j + 2], s3 = g_csr_src[j + 3];
        float n0 = g_csr_norm[j], n1 = g_csr_norm[j + 1];
        float n2 = g_csr_norm[j + 2], n3 = g_csr_norm[j + 3];
        float4 v0 = h4[(size_t)s0 * 32 + lane];
        float4 v1 = h4[(size_t)s1 * 32 + lane];
        float4 v2 = h4[(size_t)s2 * 32 + lane];
        float4 v3 = h4[(size_t)s3 * 32 + lane];
        acc.x += n0 * fmaxf(v0.x * scv.x + shv.x, 0.0f) + n1 * fmaxf(v1.x * scv.x + shv.x, 0.0f)
               + n2 * fmaxf(v2.x * scv.x + shv.x, 0.0f) + n3 * fmaxf(v3.x * scv.x + shv.x, 0.0f);
        acc.y += n0 * fmaxf(v0.y * scv.y + shv.y, 0.0f) + n1 * fmaxf(v1.y * scv.y + shv.y, 0.0f)
               + n2 * fmaxf(v2.y * scv.y + shv.y, 0.0f) + n3 * fmaxf(v3.y * scv.y + shv.y, 0.0f);
        acc.z += n0 * fmaxf(v0.z * scv.z + shv.z, 0.0f) + n1 * fmaxf(v1.z * scv.z + shv.z, 0.0f)
               + n2 * fmaxf(v2.z * scv.z + shv.z, 0.0f) + n3 * fmaxf(v3.z * scv.z + shv.z, 0.0f);
        acc.w += n0 * fmaxf(v0.w * scv.w + shv.w, 0.0f) + n1 * fmaxf(v1.w * scv.w + shv.w, 0.0f)
               + n2 * fmaxf(v2.w * scv.w + shv.w, 0.0f) + n3 * fmaxf(v3.w * scv.w + shv.w, 0.0f);
    }
    for (; j < end; j++) {
        int s0 = g_csr_src[j];
        float n0 = g_csr_norm[j];
        float4 v0 = h4[(size_t)s0 * 32 + lane];
        acc.x += n0 * fmaxf(v0.x * scv.x + shv.x, 0.0f);
        acc.y += n0 * fmaxf(v0.y * scv.y + shv.y, 0.0f);
        acc.z += n0 * fmaxf(v0.z * scv.z + shv.z, 0.0f);
        acc.w += n0 * fmaxf(v0.w * scv.w + shv.w, 0.0f);
    }
    ((float4*)out)[(size_t)node * 32 + lane] = acc;
}

// ---------------------------------------------------------------------------
// GEMM (2-col thread tile): C = A @ W + b with BN-stats epilogue.
// Thread t: row group g=t>>6 (16 rows), columns c=t&63 and c+64.
// Per kp2: 2 LDG.128 (w) + 16 LDS.128 (x) + 64 FFMA2  (1 LDS : 4 FFMA2)
// ---------------------------------------------------------------------------
template <int K>
__global__ __launch_bounds__(128) void gemm_kernel(const float* __restrict__ A,
                                                   const float* __restrict__ Wp,
                                                   const float* __restrict__ b,
                                                   float* __restrict__ C,
                                                   float* __restrict__ stats) {
    __shared__ float xs[ROWS][K];
    const int row0 = blockIdx.x * ROWS;
    const int tid = threadIdx.x;
    const int c = tid & 63;
    const int g = tid >> 6;            // 0 or 1 -> rows [g*16, g*16+16)

    const float4* A4 = (const float4*)(A + (size_t)row0 * K);
    float4* xs4 = (float4*)&xs[0][0];
#pragma unroll
    for (int i = tid; i < ROWS * K / 4; i += 128) xs4[i] = A4[i];
    __syncthreads();

    ull acc0[16], acc1[16];
#pragma unroll
    for (int r = 0; r < 16; r++) { acc0[r] = 0ULL; acc1[r] = 0ULL; }

    const ulonglong2* Wp2 = (const ulonglong2*)Wp;
#pragma unroll 2
    for (int kp2 = 0; kp2 < K / 4; kp2++) {
        ulonglong2 w0 = Wp2[kp2 * CH + c];
        ulonglong2 w1 = Wp2[kp2 * CH + c + 64];
#pragma unroll
        for (int r = 0; r < 16; r++) {
            ulonglong2 xv = *(const ulonglong2*)&xs[g * 16 + r][4 * kp2];
            acc0[r] = ffma2(xv.x, w0.x, acc0[r]);
            acc0[r] = ffma2(xv.y, w0.y, acc0[r]);
            acc1[r] = ffma2(xv.x, w1.x, acc1[r]);
            acc1[r] = ffma2(xv.y, w1.y, acc1[r]);
        }
    }

    float b0 = b[c], b1 = b[c + 64];
    float s0 = 0.0f, q0 = 0.0f, s1 = 0.0f, q1 = 0.0f;
    float* Cp = C + (size_t)(row0 + g * 16) * CH;
#pragma unroll
    for (int r = 0; r < 16; r++) {
        float v0 = unpack_sum(acc0[r]) + b0;
        float v1 = unpack_sum(acc1[r]) + b1;
        Cp[(size_t)r * CH + c] = v0;
        Cp[(size_t)r * CH + c + 64] = v1;
        s0 += v0; q0 += v0 * v0;
        s1 += v1; q1 += v1 * v1;
    }
    atomicAdd(&stats[c], s0);
    atomicAdd(&stats[CH + c], q0);
    atomicAdd(&stats[c + 64], s1);
    atomicAdd(&stats[CH + c + 64], q1);
}

// ---------------------------------------------------------------------------
// Final fused layer (2-col thread tile, dynamic smem). Also the ncu probe.
// ---------------------------------------------------------------------------
__global__ __launch_bounds__(128) void final_kernel(const float* __restrict__ h,
                                                    const float* __restrict__ dist,
                                                    const float* __restrict__ degf,
                                                    const float* __restrict__ Wd,
                                                    const float* __restrict__ bd,
                                                    const float* __restrict__ Wg,
                                                    const float* __restrict__ bg,
                                                    const float* __restrict__ Wp,
                                                    const float* __restrict__ bm,
                                                    const float* __restrict__ gamma,
                                                    const float* __restrict__ beta,
                                                    float* __restrict__ out) {
    extern __shared__ float smem[];
    float* cs = smem;                       // [ROWS][KFIN]
    float* sc = smem + ROWS * KFIN;
    float* sh = sc + CH;
    const int row0 = blockIdx.x * ROWS;
    const int tid = threadIdx.x;
    const int c = tid & 63;
    const int g = tid >> 6;

    if (tid < CH) {
        float mean = g_stats[2 * CH + tid] * (1.0f / NNODES);
        float var = g_stats[3 * CH + tid] * (1.0f / NNODES) - mean * mean;
        float scale = gamma[tid] * rsqrtf(var + 1e-5f);
        sc[tid] = scale;
        sh[tid] = beta[tid] - mean * scale;
    }
    __syncthreads();

    const float4* h4 = (const float4*)(h + (size_t)row0 * CH);
#pragma unroll
    for (int i = tid; i < ROWS * CH / 4; i += 128) {
        int r = i >> 5;
        int cc = (i & 31) * 4;
        float4 v = h4[i];
        float4 scv = *(const float4*)&sc[cc];
        float4 shv = *(const float4*)&sh[cc];
        v.x = fmaxf(v.x * scv.x + shv.x, 0.0f);
        v.y = fmaxf(v.y * scv.y + shv.y, 0.0f);
        v.z = fmaxf(v.z * scv.z + shv.z, 0.0f);
        v.w = fmaxf(v.w * scv.w + shv.w, 0.0f);
        *(float4*)&cs[r * KFIN + cc] = v;
    }
    {
        float wd = Wd[tid], bdv = bd[tid], wg = Wg[tid], bgv = bg[tid];
#pragma unroll
        for (int r = 0; r < ROWS; r++) {
            cs[r * KFIN + CH + tid] = fmaxf(dist[row0 + r] * wd + bdv, 0.0f);
            cs[r * KFIN + 2 * CH + tid] = fmaxf(degf[row0 + r] * wg + bgv, 0.0f);
        }
    }
    __syncthreads();

    ull acc0[16], acc1[16];
#pragma unroll
    for (int r = 0; r < 16; r++) { acc0[r] = 0ULL; acc1[r] = 0ULL; }

    const ulonglong2* Wp2 = (const ulonglong2*)Wp;
#pragma unroll 2
    for (int kp2 = 0; kp2 < KFIN / 4; kp2++) {
        ulonglong2 w0 = Wp2[kp2 * CH + c];
        ulonglong2 w1 = Wp2[kp2 * CH + c + 64];
        const char* xbase = (const char*)&cs[(g * 16) * KFIN + 4 * kp2];
#pragma unroll
        for (int r = 0; r < 16; r++) {
            ulonglong2 xv = *(const ulonglong2*)(xbase + (size_t)r * KFIN * 4);
            acc0[r] = ffma2(xv.x, w0.x, acc0[r]);
            acc0[r] = ffma2(xv.y, w0.y, acc0[r]);
            acc1[r] = ffma2(xv.x, w1.x, acc1[r]);
            acc1[r] = ffma2(xv.y, w1.y, acc1[r]);
        }
    }

    float b0 = bm[c], b1 = bm[c + 64];
    float* op = out + (size_t)(row0 + g * 16) * CH;
#pragma unroll
    for (int r = 0; r < 16; r++) {
        op[(size_t)r * CH + c] = unpack_sum(acc0[r]) + b0;
        op[(size_t)r * CH + c + 64] = unpack_sum(acc1[r]) + b1;
    }
}

// ---------------------------------------------------------------------------
extern "C" void kernel_launch(void* const* d_in, const int* in_sizes, int n_in,
                              void* d_out, int out_size) {
    const float* x     = (const float*)d_in[0];
    const void*  ei    = d_in[1];
    const float* ew    = (const float*)d_in[2];
    const float* dist  = (const float*)d_in[3];
    const float* degf  = (const float*)d_in[4];
    const float* W1    = (const float*)d_in[5];
    const float* b1    = (const float*)d_in[6];
    const float* W2    = (const float*)d_in[7];
    const float* b2    = (const float*)d_in[8];
    const float* g1    = (const float*)d_in[9];
    const float* be1   = (const float*)d_in[10];
    const float* g2    = (const float*)d_in[11];
    const float* be2   = (const float*)d_in[12];
    const float* Wd    = (const float*)d_in[13];
    const float* bd    = (const float*)d_in[14];
    const float* Wg    = (const float*)d_in[15];
    const float* bg    = (const float*)d_in[16];
    const float* Wm    = (const float*)d_in[17];
    const float* bm    = (const float*)d_in[18];
    float* out = (float*)d_out;

    float *bufA, *bufB, *stats, *Wp1, *Wp2, *Wpm;
    cudaGetSymbolAddress((void**)&bufA, g_bufA);
    cudaGetSymbolAddress((void**)&bufB, g_bufB);
    cudaGetSymbolAddress((void**)&stats, g_stats);
    cudaGetSymbolAddress((void**)&Wp1, g_Wp1);
    cudaGetSymbolAddress((void**)&Wp2, g_Wp2);
    cudaGetSymbolAddress((void**)&Wpm, g_Wpm);

    const int nodeBlocks = (NNODES + 255) / 256;
    const int edgeBlocks = (NEDGES + 255) / 256;
    const int rowBlocks  = NNODES / ROWS;
    const int agg128Blocks = (NNODES * 32 + 255) / 256;
    const int agg64Blocks  = ((NNODES + 1) / 2 * 32 + 255) / 256;
    const int FIN_SMEM = (ROWS * KFIN + 2 * CH) * 4;

    cudaFuncSetAttribute(final_kernel, cudaFuncAttributeMaxDynamicSharedMemorySize, FIN_SMEM);

    // slots 1-3
    detect_idx_kernel<<<1, 256>>>((const int*)ei);
    deg_init_kernel<<<nodeBlocks, 256>>>();
    pack_kernel<<<160, 256>>>(W1, W2, Wm);

    // slot 4: ncu PROBE of final_kernel (grid-limited; d_out overwritten below)
    final_kernel<<<256, 128, FIN_SMEM>>>(bufB, dist, degf, Wd, bd, Wg, bg,
                                         Wpm, bm, g2, be2, out);

    // --- gcn_norm + CSR build ---
    deg_count_kernel<<<edgeBlocks, 256>>>(ei, ew);
    scanA_kernel<<<SCAN_BLOCKS, SCAN_BT>>>();
    scanB_kernel<<<1, 256>>>();
    scanC_kernel<<<SCAN_BLOCKS, SCAN_BT>>>();
    fill_kernel<<<edgeBlocks, 256>>>(ei, ew);

    // --- layer 1 ---
    agg64_kernel<<<agg64Blocks, 256>>>(x, bufA);
    gemm_kernel<CIN><<<rowBlocks, 128>>>(bufA, Wp1, b1, bufB, stats);

    // --- layer 2 ---
    agg_bn_kernel<<<agg128Blocks, 256>>>(bufB, g1, be1, bufA);
    gemm_kernel<CH><<<rowBlocks, 128>>>(bufA, Wp2, b2, bufB, stats + 2 * CH);

    // --- final ---
    final_kernel<<<rowBlocks, 128, FIN_SMEM>>>(bufB, dist, degf, Wd, bd, Wg, bg,
                                               Wpm, bm, g2, be2, out);
}